// round 16
// baseline (speedup 1.0000x reference)
#include <cuda_runtime.h>
#include <cuda_bf16.h>
#include <stdint.h>
#include <math.h>

#define B_ 4
#define N_ 4
#define C_ 256
#define H_ 100
#define W_ 152
#define HW_ (H_*W_)
#define PPAD 15360           // 120 tiles of 128 px

// ---------------- device scratch (no allocations allowed) ----------------
__device__ float g_S   [B_*(N_+1)*HW_];
__device__ int   g_mism[B_*N_*HW_];
__device__ __nv_bfloat16 g_whi[C_*C_];
__device__ __nv_bfloat16 g_wlo[C_*C_];
__device__ __nv_bfloat16 g_fhiT[(size_t)B_*PPAD*C_];   // fused^T hi [b][p][c]
__device__ __nv_bfloat16 g_floT[(size_t)B_*PPAD*C_];   // fused^T lo [b][p][c]

__device__ __forceinline__ uint32_t smem_u32(const void* p) {
    uint32_t a;
    asm("{ .reg .u64 t; cvta.to.shared.u64 t, %1; cvt.u32.u64 %0, t; }" : "=r"(a) : "l"(p));
    return a;
}
#define CP_ASYNC16(dst, src) \
    asm volatile("cp.async.cg.shared.global [%0], [%1], 16;" :: "r"(dst), "l"(src))
#define CP_COMMIT() asm volatile("cp.async.commit_group;" ::: "memory")
#define CP_WAIT(n)  asm volatile("cp.async.wait_group %0;" :: "n"(n) : "memory")

__device__ __forceinline__ void mma16816(float* d, const uint32_t* a, const uint32_t* b) {
    asm volatile("mma.sync.aligned.m16n8k16.row.col.f32.bf16.bf16.f32 "
        "{%0,%1,%2,%3}, {%4,%5,%6,%7}, {%8,%9}, {%0,%1,%2,%3};"
        : "+f"(d[0]), "+f"(d[1]), "+f"(d[2]), "+f"(d[3])
        : "r"(a[0]), "r"(a[1]), "r"(a[2]), "r"(a[3]), "r"(b[0]), "r"(b[1]));
}
#define LDSM4(r0,r1,r2,r3, addr) \
    asm volatile("ldmatrix.sync.aligned.m8n8.x4.shared.b16 {%0,%1,%2,%3}, [%4];" \
        : "=r"(r0),"=r"(r1),"=r"(r2),"=r"(r3) : "r"(addr))
#define LDSM2(r0,r1, addr) \
    asm volatile("ldmatrix.sync.aligned.m8n8.x2.shared.b16 {%0,%1}, [%2];" \
        : "=r"(r0),"=r"(r1) : "r"(addr))

// Explicit PRMT (default mode): selector nibble bit 3 = sign-replicate the
// selected byte's MSB across the output byte (PTX ISA documented). The
// __byte_perm intrinsic may mask this mode bit — hence raw asm.
__device__ __forceinline__ unsigned prmt_sign2(unsigned a, unsigned b) {
    unsigned r;
    asm("prmt.b32 %0, %1, %2, 0x00FB;" : "=r"(r) : "r"(a), "r"(b));
    return r;   // byte0 = 0xFF iff sign(a), byte1 = 0xFF iff sign(b)
}
__device__ __forceinline__ unsigned prmt_sign1(unsigned a) {
    unsigned r;
    asm("prmt.b32 %0, %1, %1, 0x000B;" : "=r"(r) : "r"(a));
    return r;   // byte0 = 0xFF iff sign(a); bytes1-3 garbage (masked by dp4a)
}
// Pack sign bytes of 4 words: out = [sgn(a), sgn(b), sgn(c), sgn(d)] (3 PRMT)
__device__ __forceinline__ unsigned prmt_merge4(unsigned a, unsigned b,
                                                unsigned c, unsigned d) {
    unsigned p = prmt_sign2(a, b);
    unsigned q = prmt_sign2(c, d);
    unsigned r;
    asm("prmt.b32 %0, %1, %2, 0x5410;" : "=r"(r) : "r"(p), "r"(q));
    return r;
}

// ---------------------------------------------------------------------------
// K0: split W into bf16 hi/lo
// ---------------------------------------------------------------------------
__global__ __launch_bounds__(256) void wprep_kernel(const float* __restrict__ w) {
    int i = blockIdx.x * 256 + threadIdx.x;
    float v = w[i];
    __nv_bfloat16 hi = __float2bfloat16(v);
    g_whi[i] = hi;
    g_wlo[i] = __float2bfloat16(v - __bfloat162float(hi));
}

// zero mismatch accumulators (graph replays must be deterministic)
__global__ __launch_bounds__(256) void zero_mism() {
    int i = blockIdx.x * 256 + threadIdx.x;
    if (i < B_*N_*HW_) g_mism[i] = 0;
}

// ---------------------------------------------------------------------------
// K1: per-pixel channel sum, float4 over pixels; per-component the add order
// is sequential ascending c — bit-exact vs reference.
// ---------------------------------------------------------------------------
#define HW4 (HW_/4)
__global__ __launch_bounds__(256) void sum_kernel(const float* __restrict__ feat,
                                                  const float* __restrict__ nearby) {
    int p4 = blockIdx.x * blockDim.x + threadIdx.x;
    int m = blockIdx.y;
    if (p4 >= HW4) return;
    int b = m / (N_+1), t = m % (N_+1);
    const float* srcf = (t == 0) ? (feat + (size_t)b * C_ * HW_)
                                 : (nearby + (size_t)(b * N_ + (t-1)) * C_ * HW_);
    const float4* src = (const float4*)srcf + p4;
    float ax = 0.f, ay = 0.f, az = 0.f, aw = 0.f;
    #pragma unroll 1
    for (int c0 = 0; c0 < C_; c0 += 8) {
        float4 v[8];
        #pragma unroll
        for (int k = 0; k < 8; k++) v[k] = src[(size_t)(c0 + k) * HW4];
        #pragma unroll
        for (int k = 0; k < 8; k++) {
            ax += v[k].x; ay += v[k].y; az += v[k].z; aw += v[k].w;
        }
    }
    ((float4*)(g_S + (size_t)m * HW_))[p4] = make_float4(ax, ay, az, aw);
}

// 3x3 edge-clamped box average of g_S map m at (i,j) — identical op order to
// the reference (di-major, then dj; single multiply by fp32(1/2304)).
__device__ __forceinline__ float box_avg(const float* __restrict__ S, int i, int j) {
    float acc = 0.0f;
    #pragma unroll
    for (int di = 0; di < 3; di++) {
        int y = min(max(i + di - 1, 0), H_ - 1);
        #pragma unroll
        for (int dj = 0; dj < 3; dj++) {
            int x = min(max(j + dj - 1, 0), W_ - 1);
            acc += S[y * W_ + x];
        }
    }
    return acc * (1.0f / 2304.0f);
}

// ---------------------------------------------------------------------------
// K3: census mismatch counts; packed sign-bytes per plane (PRMT merge) then
// 3 XOR + 3 DP4A per n. 2 px/thread, 16B cp.async, 3-slot ring, 1 bar/chan.
// ---------------------------------------------------------------------------
#define TW 32
#define TH 16
#define SROW 40                        // floats per smem row (aligned 160B)
#define PROWS 18                       // halo rows per plane
#define PLANEF (PROWS*SROW)            // 720
#define CHF (5*PLANEF)                 // 3600 floats per channel
#define LOADS (5*PROWS*10)             // 900 uint4 per channel
#define CHUNK 32

__global__ __launch_bounds__(256, 3) void sim_kernel(const float* __restrict__ feat,
                                                     const float* __restrict__ nearby) {
    __shared__ float sm[3][CHF];       // 43.2 KB triple-buffer ring

    int tid = threadIdx.x;
    int tx = tid & 31;
    int ty = tid >> 5;                 // 0..7
    int j0 = blockIdx.x * TW, i0 = blockIdx.y * TH;
    int bz = blockIdx.z;
    int b  = bz >> 3;
    int c0 = (bz & 7) * CHUNK;
    int iA = i0 + 2*ty, iB = iA + 1;
    int j  = j0 + tx;
    bool vA = (iA < H_) && (j < W_);
    bool vB = (iB < H_) && (j < W_);
    int pA = iA * W_ + j, pB = pA + W_;

    int xlo = max(j0 - 4, 0);
    int sx0 = min(max(j - 1, 0), W_-1) - xlo;
    int sx1 = min(max(j    , 0), W_-1) - xlo;
    int sx2 = min(max(j + 1, 0), W_-1) - xlo;

    // cooperative loader: 900 uint4 per channel, 4 slots/thread
    const float* fbase = feat   + ((size_t)b * C_ + c0) * HW_;
    const float* nbase = nearby + ((size_t)(b * N_) * C_ + c0) * HW_;
    const float* lptr[4];
    uint32_t sdst[4];
    uint32_t smbase = smem_u32(&sm[0][0]);
    #pragma unroll
    for (int q = 0; q < 4; q++) {
        int idx = tid + q * 256;
        if (idx < LOADS) {
            int row = idx / 10, ch = idx % 10;
            int t = row / PROWS, r = row % PROWS;
            int gy = min(max(i0 + r - 1, 0), H_ - 1);
            int xs = min(xlo + ch * 4, W_ - 4);      // stay in-plane; extra slots unused
            const float* base = (t == 0) ? fbase : (nbase + (size_t)(t - 1) * C_ * HW_);
            lptr[q] = base + gy * W_ + xs;
            sdst[q] = smbase + (uint32_t)(t * PLANEF + r * SROW + ch * 4) * 4u;
        } else {
            lptr[q] = fbase;
            sdst[q] = smbase;
        }
    }
    bool q3 = (tid + 3*256) < LOADS;

    // prefetch channels 0 and 1 (overlaps the threshold math below)
    #pragma unroll
    for (int s = 0; s < 2; s++) {
        uint32_t soff = (uint32_t)s * (CHF * 4u);
        size_t goff = (size_t)s * HW_;
        #pragma unroll
        for (int q = 0; q < 3; q++) CP_ASYNC16(sdst[q] + soff, lptr[q] + goff);
        if (q3) CP_ASYNC16(sdst[3] + soff, lptr[3] + goff);
        CP_COMMIT();
    }

    // census thresholds: inline 3x3 box average of g_S (bit-exact ref order)
    float T1a = 0.f, T1b = 0.f, T2a[N_] = {0,0,0,0}, T2b[N_] = {0,0,0,0};
    if (vA) {
        T1a = box_avg(g_S + (size_t)(b*5 + 0) * HW_, iA, j);
        #pragma unroll
        for (int n = 0; n < N_; n++)
            T2a[n] = box_avg(g_S + (size_t)(b*5 + 1 + n) * HW_, iA, j);
    }
    if (vB) {
        T1b = box_avg(g_S + (size_t)(b*5 + 0) * HW_, iB, j);
        #pragma unroll
        for (int n = 0; n < N_; n++)
            T2b[n] = box_avg(g_S + (size_t)(b*5 + 1 + n) * HW_, iB, j);
    }

    // mA/mB accumulate NEGATIVE mismatch counts via signed dp4a
    int mA[N_] = {0,0,0,0}, mB[N_] = {0,0,0,0};

    #pragma unroll 1
    for (int c = 0; c < CHUNK; c++) {
        CP_WAIT(1);
        __syncthreads();

        if (c + 2 < CHUNK) {
            uint32_t soff = (uint32_t)((c + 2) % 3) * (CHF * 4u);
            size_t goff = (size_t)(c + 2) * HW_;
            #pragma unroll
            for (int q = 0; q < 3; q++) CP_ASYNC16(sdst[q] + soff, lptr[q] + goff);
            if (q3) CP_ASYNC16(sdst[3] + soff, lptr[3] + goff);
        }
        CP_COMMIT();

        const float* S = &sm[c % 3][0] + (2 * ty) * SROW;

        // feature plane: packed sign bytes for both pixels (7 PRMT each)
        unsigned fA0, fA1, fA2, fB0, fB1, fB2;
        {
            float x[4][3];
            #pragma unroll
            for (int rr = 0; rr < 4; rr++) {
                x[rr][0] = S[rr * SROW + sx0];
                x[rr][1] = S[rr * SROW + sx1];
                x[rr][2] = S[rr * SROW + sx2];
            }
            unsigned uA[9], uB[9];
            #pragma unroll
            for (int dy = 0; dy < 3; dy++)
                #pragma unroll
                for (int dx = 0; dx < 3; dx++) {
                    uA[dy*3+dx] = __float_as_uint(x[dy  ][dx] - T1a);
                    uB[dy*3+dx] = __float_as_uint(x[dy+1][dx] - T1b);
                }
            fA0 = prmt_merge4(uA[0], uA[1], uA[2], uA[3]);
            fA1 = prmt_merge4(uA[4], uA[5], uA[6], uA[7]);
            fA2 = prmt_sign1(uA[8]);
            fB0 = prmt_merge4(uB[0], uB[1], uB[2], uB[3]);
            fB1 = prmt_merge4(uB[4], uB[5], uB[6], uB[7]);
            fB2 = prmt_sign1(uB[8]);
        }
        #pragma unroll
        for (int n = 0; n < N_; n++) {
            const float* Sn = S + (1 + n) * PLANEF;
            float x[4][3];
            #pragma unroll
            for (int rr = 0; rr < 4; rr++) {
                x[rr][0] = Sn[rr * SROW + sx0];
                x[rr][1] = Sn[rr * SROW + sx1];
                x[rr][2] = Sn[rr * SROW + sx2];
            }
            unsigned vAa[9], vBb[9];
            #pragma unroll
            for (int dy = 0; dy < 3; dy++)
                #pragma unroll
                for (int dx = 0; dx < 3; dx++) {
                    int k = dy*3 + dx;
                    vAa[k] = __float_as_uint(x[dy  ][dx] - T2a[n]);
                    vBb[k] = __float_as_uint(x[dy+1][dx] - T2b[n]);
                }
            unsigned a0 = prmt_merge4(vAa[0], vAa[1], vAa[2], vAa[3]);
            unsigned a1 = prmt_merge4(vAa[4], vAa[5], vAa[6], vAa[7]);
            unsigned a2 = prmt_sign1(vAa[8]);
            unsigned b0 = prmt_merge4(vBb[0], vBb[1], vBb[2], vBb[3]);
            unsigned b1 = prmt_merge4(vBb[4], vBb[5], vBb[6], vBb[7]);
            unsigned b2 = prmt_sign1(vBb[8]);
            // XOR of 0x00/0xFF sign bytes = 0xFF per mismatch; dp4a adds -1 each.
            mA[n] = __dp4a((int)(a0 ^ fA0), 0x01010101, mA[n]);
            mA[n] = __dp4a((int)(a1 ^ fA1), 0x01010101, mA[n]);
            mA[n] = __dp4a((int)(a2 ^ fA2), 0x00000001, mA[n]);
            mB[n] = __dp4a((int)(b0 ^ fB0), 0x01010101, mB[n]);
            mB[n] = __dp4a((int)(b1 ^ fB1), 0x01010101, mB[n]);
            mB[n] = __dp4a((int)(b2 ^ fB2), 0x00000001, mB[n]);
        }
    }

    if (vA) {
        #pragma unroll
        for (int n = 0; n < N_; n++)
            atomicAdd(&g_mism[(size_t)(b * N_ + n) * HW_ + pA], -mA[n]);
    }
    if (vB) {
        #pragma unroll
        for (int n = 0; n < N_; n++)
            atomicAdd(&g_mism[(size_t)(b * N_ + n) * HW_ + pB], -mB[n]);
    }
}

// ---------------------------------------------------------------------------
// K4: softmax + weighted fuse; writes bf16 hi/lo TRANSPOSED [b][p][c]
// ---------------------------------------------------------------------------
__global__ __launch_bounds__(256) void fuse_kernel(const float* __restrict__ feat,
                                                   const float* __restrict__ nearby) {
    __shared__ float4 w_s[32];
    __shared__ __nv_bfloat16 s_hi[32][258];
    __shared__ __nv_bfloat16 s_lo[32][258];

    int tid = threadIdx.x;
    int b = blockIdx.y;
    int p0 = blockIdx.x * 32;

    if (tid < 32) {
        int p = p0 + tid;
        int m0 = g_mism[(size_t)(b*N_+0)*HW_ + p];
        int m1 = g_mism[(size_t)(b*N_+1)*HW_ + p];
        int m2 = g_mism[(size_t)(b*N_+2)*HW_ + p];
        int m3 = g_mism[(size_t)(b*N_+3)*HW_ + p];
        int mn = min(min(m0, m1), min(m2, m3));
        float e0 = expf((float)(mn - m0));
        float e1 = expf((float)(mn - m1));
        float e2 = expf((float)(mn - m2));
        float e3 = expf((float)(mn - m3));
        float s = e0 + e1 + e2 + e3;
        w_s[tid] = make_float4(e0 / s, e1 / s, e2 / s, e3 / s);
    }
    __syncthreads();

    int c   = tid >> 3;
    int px0 = (tid & 7) * 4;
    const float* fp = feat   + (size_t)b * C_ * HW_ + p0 + px0;
    const float* np = nearby + (size_t)b * N_ * C_ * HW_ + p0 + px0;
    float4 wv[4] = {w_s[px0], w_s[px0+1], w_s[px0+2], w_s[px0+3]};

    #pragma unroll
    for (int cc = 0; cc < 8; cc++) {
        int cg = cc * 32 + c;
        size_t co = (size_t)cg * HW_;
        float4 fv = *(const float4*)(fp + co);
        float4 a0 = *(const float4*)(np + co);
        float4 a1 = *(const float4*)(np + (size_t)C_ * HW_ + co);
        float4 a2 = *(const float4*)(np + (size_t)2 * C_ * HW_ + co);
        float4 a3 = *(const float4*)(np + (size_t)3 * C_ * HW_ + co);
        float fr[4] = {fv.x, fv.y, fv.z, fv.w};
        float r0[4] = {a0.x, a0.y, a0.z, a0.w};
        float r1[4] = {a1.x, a1.y, a1.z, a1.w};
        float r2[4] = {a2.x, a2.y, a2.z, a2.w};
        float r3[4] = {a3.x, a3.y, a3.z, a3.w};
        #pragma unroll
        for (int e = 0; e < 4; e++) {
            float4 w = wv[e];
            float v = w.x * r0[e];
            v = fmaf(w.y, r1[e], v);
            v = fmaf(w.z, r2[e], v);
            v = fmaf(w.w, r3[e], v);
            v += fr[e];
            __nv_bfloat16 hi = __float2bfloat16(v);
            s_hi[px0 + e][cg] = hi;
            s_lo[px0 + e][cg] = __float2bfloat16(v - __bfloat162float(hi));
        }
    }
    __syncthreads();

    uint32_t* dh = (uint32_t*)g_fhiT + ((size_t)b * PPAD + p0) * (C_/2);
    uint32_t* dl = (uint32_t*)g_floT + ((size_t)b * PPAD + p0) * (C_/2);
    #pragma unroll
    for (int q = 0; q < 16; q++) {
        int w = tid + q * 256;
        int row = w >> 7, cw = w & 127;
        dh[(size_t)row * 128 + cw] = *(const uint32_t*)&s_hi[row][cw * 2];
        dl[(size_t)row * 128 + cw] = *(const uint32_t*)&s_lo[row][cw * 2];
    }
}

// ---------------------------------------------------------------------------
// K5: mma.sync bf16 split GEMM with ldmatrix fragment loads.
// out[b][o][p] = sum_c W[o][c]*F[c][p] + bias[o]
// ---------------------------------------------------------------------------
#define WPITCH 36                       // 32-bit words per smem row
#define ROWB   144                      // bytes per smem row
#define ST_A   18432                    // 128*144 bytes
#define STAGE  36864                    // A + B per stage
#define GEMM_SMEM (2*STAGE)             // 73728

__global__ __launch_bounds__(256, 2)
void gemm_kernel(const float* __restrict__ bias, float* __restrict__ out) {
    extern __shared__ char smem[];
    uint32_t sb = smem_u32(smem);

    int tid = threadIdx.x, wid = tid >> 5, lid = tid & 31;
    int g = lid >> 2, t = lid & 3;
    int wm = wid & 1, wn = wid >> 1;
    int p0 = blockIdx.x * 128, o0 = blockIdx.y * 128, b = blockIdx.z;

    int ldrow = tid >> 3, ldcol = tid & 7;

    int lm = lid >> 3, lr = lid & 7;
    int a_row_l = wm * 64 + (lm & 1) * 8 + lr;
    int a_col_b = ((lm >> 1) * 4) * 4;
    int b_row_l = wn * 32 + lr;
    int b_col_b = ((lm & 1) * 4) * 4;

    float acc[4][4][4];
    #pragma unroll
    for (int i = 0; i < 4; i++)
        #pragma unroll
        for (int j = 0; j < 4; j++)
            #pragma unroll
            for (int k = 0; k < 4; k++) acc[i][j][k] = 0.0f;

    auto load_chunk = [&](int kk) {
        int buf = kk & 1, seg = kk >> 2, cc0 = (kk & 3) * 64;
        const __nv_bfloat16* As = (seg < 2) ? g_whi : g_wlo;
        const __nv_bfloat16* Bs = (seg == 1) ? g_floT : g_fhiT;
        uint32_t da = sb + buf * STAGE;
        uint32_t db = da + ST_A;
        const __nv_bfloat16* ga = As + (size_t)(o0 + ldrow) * C_ + cc0 + ldcol * 8;
        const __nv_bfloat16* gb = Bs + ((size_t)b * PPAD + p0 + ldrow) * C_ + cc0 + ldcol * 8;
        #pragma unroll
        for (int q = 0; q < 4; q++) {
            CP_ASYNC16(da + (ldrow + q*32) * ROWB + ldcol * 16, ga + (size_t)(q*32) * C_);
            CP_ASYNC16(db + (ldrow + q*32) * ROWB + ldcol * 16, gb + (size_t)(q*32) * C_);
        }
        CP_COMMIT();
    };

    load_chunk(0);

    for (int kk = 0; kk < 12; kk++) {
        if (kk + 1 < 12) { load_chunk(kk + 1); CP_WAIT(1); }
        else             { CP_WAIT(0); }
        __syncthreads();

        uint32_t Abase = sb + (kk & 1) * STAGE;
        uint32_t Bbase = Abase + ST_A;

        #pragma unroll
        for (int s = 0; s < 4; s++) {
            uint32_t afr[4][4];
            #pragma unroll
            for (int mf = 0; mf < 4; mf++) {
                uint32_t aaddr = Abase + (uint32_t)((a_row_l + mf*16) * ROWB + s*32 + a_col_b);
                LDSM4(afr[mf][0], afr[mf][1], afr[mf][2], afr[mf][3], aaddr);
            }
            uint32_t bfr[4][2];
            #pragma unroll
            for (int nf = 0; nf < 4; nf++) {
                uint32_t baddr = Bbase + (uint32_t)((b_row_l + nf*8) * ROWB + s*32 + b_col_b);
                LDSM2(bfr[nf][0], bfr[nf][1], baddr);
            }
            #pragma unroll
            for (int mf = 0; mf < 4; mf++)
                #pragma unroll
                for (int nf = 0; nf < 4; nf++)
                    mma16816(acc[mf][nf], afr[mf], bfr[nf]);
        }
        __syncthreads();
    }

    #pragma unroll
    for (int mf = 0; mf < 4; mf++) {
        int o  = o0 + wm * 64 + mf * 16 + g;
        float bv0 = bias[o];
        float bv1 = bias[o + 8];
        float* r0 = out + ((size_t)b * C_ + o    ) * HW_;
        float* r1 = out + ((size_t)b * C_ + o + 8) * HW_;
        #pragma unroll
        for (int nf = 0; nf < 4; nf++) {
            int p = p0 + wn * 32 + nf * 8 + 2 * t;
            if (p < HW_) {
                *(float2*)(r0 + p) = make_float2(acc[mf][nf][0] + bv0, acc[mf][nf][1] + bv0);
                *(float2*)(r1 + p) = make_float2(acc[mf][nf][2] + bv1, acc[mf][nf][3] + bv1);
            }
        }
    }
}

// ---------------------------------------------------------------------------
extern "C" void kernel_launch(void* const* d_in, const int* in_sizes, int n_in,
                              void* d_out, int out_size) {
    const float* feat   = (const float*)d_in[0];
    const float* nearby = (const float*)d_in[1];
    const float* wf     = (const float*)d_in[2];
    const float* bf     = (const float*)d_in[3];
    float* out = (float*)d_out;

    cudaFuncSetAttribute(gemm_kernel, cudaFuncAttributeMaxDynamicSharedMemorySize, GEMM_SMEM);

    wprep_kernel<<<C_*C_/256, 256>>>(wf);
    zero_mism<<<(B_*N_*HW_ + 255)/256, 256>>>();

    dim3 g1((HW4 + 255) / 256, B_ * (N_ + 1));
    sum_kernel<<<g1, 256>>>(feat, nearby);

    dim3 g3((W_ + TW - 1) / TW, (H_ + TH - 1) / TH, B_ * 8);
    sim_kernel<<<g3, 256>>>(feat, nearby);

    dim3 g4(HW_ / 32, B_);
    fuse_kernel<<<g4, 256>>>(feat, nearby);

    dim3 g5(PPAD / 128, C_ / 128, B_);
    gemm_kernel<<<g5, 256, GEMM_SMEM>>>(bf, out);
}

// round 17
// speedup vs baseline: 1.0212x; 1.0212x over previous
#include <cuda_runtime.h>
#include <cuda_bf16.h>
#include <stdint.h>
#include <math.h>

#define B_ 4
#define N_ 4
#define C_ 256
#define H_ 100
#define W_ 152
#define HW_ (H_*W_)
#define PPAD 15360           // 120 tiles of 128 px

// ---------------- device scratch (no allocations allowed) ----------------
__device__ float g_S   [B_*(N_+1)*HW_];
__device__ int   g_mism[B_*N_*HW_];
__device__ __nv_bfloat16 g_whi[C_*C_];
__device__ __nv_bfloat16 g_wlo[C_*C_];
__device__ __nv_bfloat16 g_fhiT[(size_t)B_*PPAD*C_];   // fused^T hi [b][p][c]
__device__ __nv_bfloat16 g_floT[(size_t)B_*PPAD*C_];   // fused^T lo [b][p][c]

__device__ __forceinline__ uint32_t smem_u32(const void* p) {
    uint32_t a;
    asm("{ .reg .u64 t; cvta.to.shared.u64 t, %1; cvt.u32.u64 %0, t; }" : "=r"(a) : "l"(p));
    return a;
}
#define CP_ASYNC16(dst, src) \
    asm volatile("cp.async.cg.shared.global [%0], [%1], 16;" :: "r"(dst), "l"(src))
#define CP_COMMIT() asm volatile("cp.async.commit_group;" ::: "memory")
#define CP_WAIT(n)  asm volatile("cp.async.wait_group %0;" :: "n"(n) : "memory")

__device__ __forceinline__ void mma16816(float* d, const uint32_t* a, const uint32_t* b) {
    asm volatile("mma.sync.aligned.m16n8k16.row.col.f32.bf16.bf16.f32 "
        "{%0,%1,%2,%3}, {%4,%5,%6,%7}, {%8,%9}, {%0,%1,%2,%3};"
        : "+f"(d[0]), "+f"(d[1]), "+f"(d[2]), "+f"(d[3])
        : "r"(a[0]), "r"(a[1]), "r"(a[2]), "r"(a[3]), "r"(b[0]), "r"(b[1]));
}
#define LDSM4(r0,r1,r2,r3, addr) \
    asm volatile("ldmatrix.sync.aligned.m8n8.x4.shared.b16 {%0,%1,%2,%3}, [%4];" \
        : "=r"(r0),"=r"(r1),"=r"(r2),"=r"(r3) : "r"(addr))
#define LDSM2(r0,r1, addr) \
    asm volatile("ldmatrix.sync.aligned.m8n8.x2.shared.b16 {%0,%1}, [%2];" \
        : "=r"(r0),"=r"(r1) : "r"(addr))

// Explicit PRMT (default mode): selector nibble bit 3 = sign-replicate the
// selected byte's MSB across the output byte (PTX ISA documented). The
// __byte_perm intrinsic may mask this mode bit — hence raw asm.
__device__ __forceinline__ unsigned prmt_sign2(unsigned a, unsigned b) {
    unsigned r;
    asm("prmt.b32 %0, %1, %2, 0x00FB;" : "=r"(r) : "r"(a), "r"(b));
    return r;   // byte0 = 0xFF iff sign(a), byte1 = 0xFF iff sign(b)
}
__device__ __forceinline__ unsigned prmt_sign1(unsigned a) {
    unsigned r;
    asm("prmt.b32 %0, %1, %1, 0x000B;" : "=r"(r) : "r"(a));
    return r;   // byte0 = 0xFF iff sign(a); bytes1-3 garbage (masked by dp4a)
}
// Pack sign bytes of 4 words: out = [sgn(a), sgn(b), sgn(c), sgn(d)] (3 PRMT)
__device__ __forceinline__ unsigned prmt_merge4(unsigned a, unsigned b,
                                                unsigned c, unsigned d) {
    unsigned p = prmt_sign2(a, b);
    unsigned q = prmt_sign2(c, d);
    unsigned r;
    asm("prmt.b32 %0, %1, %2, 0x5410;" : "=r"(r) : "r"(p), "r"(q));
    return r;
}

// ---------------------------------------------------------------------------
// K0: split W into bf16 hi/lo
// ---------------------------------------------------------------------------
__global__ __launch_bounds__(256) void wprep_kernel(const float* __restrict__ w) {
    int i = blockIdx.x * 256 + threadIdx.x;
    float v = w[i];
    __nv_bfloat16 hi = __float2bfloat16(v);
    g_whi[i] = hi;
    g_wlo[i] = __float2bfloat16(v - __bfloat162float(hi));
}

// zero mismatch accumulators (graph replays must be deterministic)
__global__ __launch_bounds__(256) void zero_mism() {
    int i = blockIdx.x * 256 + threadIdx.x;
    if (i < B_*N_*HW_) g_mism[i] = 0;
}

// ---------------------------------------------------------------------------
// K1: per-pixel channel sum, float4 over pixels; per-component the add order
// is sequential ascending c — bit-exact vs reference.
// ---------------------------------------------------------------------------
#define HW4 (HW_/4)
__global__ __launch_bounds__(256) void sum_kernel(const float* __restrict__ feat,
                                                  const float* __restrict__ nearby) {
    int p4 = blockIdx.x * blockDim.x + threadIdx.x;
    int m = blockIdx.y;
    if (p4 >= HW4) return;
    int b = m / (N_+1), t = m % (N_+1);
    const float* srcf = (t == 0) ? (feat + (size_t)b * C_ * HW_)
                                 : (nearby + (size_t)(b * N_ + (t-1)) * C_ * HW_);
    const float4* src = (const float4*)srcf + p4;
    float ax = 0.f, ay = 0.f, az = 0.f, aw = 0.f;
    #pragma unroll 1
    for (int c0 = 0; c0 < C_; c0 += 8) {
        float4 v[8];
        #pragma unroll
        for (int k = 0; k < 8; k++) v[k] = src[(size_t)(c0 + k) * HW4];
        #pragma unroll
        for (int k = 0; k < 8; k++) {
            ax += v[k].x; ay += v[k].y; az += v[k].z; aw += v[k].w;
        }
    }
    ((float4*)(g_S + (size_t)m * HW_))[p4] = make_float4(ax, ay, az, aw);
}

// 3x3 edge-clamped box average of g_S map m at (i,j) — identical op order to
// the reference (di-major, then dj; single multiply by fp32(1/2304)).
__device__ __forceinline__ float box_avg(const float* __restrict__ S, int i, int j) {
    float acc = 0.0f;
    #pragma unroll
    for (int di = 0; di < 3; di++) {
        int y = min(max(i + di - 1, 0), H_ - 1);
        #pragma unroll
        for (int dj = 0; dj < 3; dj++) {
            int x = min(max(j + dj - 1, 0), W_ - 1);
            acc += S[y * W_ + x];
        }
    }
    return acc * (1.0f / 2304.0f);
}

// ---------------------------------------------------------------------------
// K3: census mismatch counts; packed sign-bytes per plane (PRMT merge) then
// 3 XOR + 3 DP4A per n. 2 px/thread, 16B cp.async, 3-slot ring, 1 bar/chan.
// Census compute is predicated on warp-uniform pixel validity (tail tiles).
// ---------------------------------------------------------------------------
#define TW 32
#define TH 16
#define SROW 40                        // floats per smem row (aligned 160B)
#define PROWS 18                       // halo rows per plane
#define PLANEF (PROWS*SROW)            // 720
#define CHF (5*PLANEF)                 // 3600 floats per channel
#define LOADS (5*PROWS*10)             // 900 uint4 per channel
#define CHUNK 32

__global__ __launch_bounds__(256, 3) void sim_kernel(const float* __restrict__ feat,
                                                     const float* __restrict__ nearby) {
    __shared__ float sm[3][CHF];       // 43.2 KB triple-buffer ring

    int tid = threadIdx.x;
    int tx = tid & 31;
    int ty = tid >> 5;                 // 0..7
    int j0 = blockIdx.x * TW, i0 = blockIdx.y * TH;
    int bz = blockIdx.z;
    int b  = bz >> 3;
    int c0 = (bz & 7) * CHUNK;
    int iA = i0 + 2*ty, iB = iA + 1;
    int j  = j0 + tx;
    bool vA = (iA < H_) && (j < W_);
    bool vB = (iB < H_) && (j < W_);
    bool act = vA || vB;               // warp-uniform (iA depends only on ty)
    int pA = iA * W_ + j, pB = pA + W_;

    int xlo = max(j0 - 4, 0);
    int sx0 = min(max(j - 1, 0), W_-1) - xlo;
    int sx1 = min(max(j    , 0), W_-1) - xlo;
    int sx2 = min(max(j + 1, 0), W_-1) - xlo;

    // cooperative loader: 900 uint4 per channel, 4 slots/thread
    const float* fbase = feat   + ((size_t)b * C_ + c0) * HW_;
    const float* nbase = nearby + ((size_t)(b * N_) * C_ + c0) * HW_;
    const float* lptr[4];
    uint32_t sdst[4];
    uint32_t smbase = smem_u32(&sm[0][0]);
    #pragma unroll
    for (int q = 0; q < 4; q++) {
        int idx = tid + q * 256;
        if (idx < LOADS) {
            int row = idx / 10, ch = idx % 10;
            int t = row / PROWS, r = row % PROWS;
            int gy = min(max(i0 + r - 1, 0), H_ - 1);
            int xs = min(xlo + ch * 4, W_ - 4);      // stay in-plane; extra slots unused
            const float* base = (t == 0) ? fbase : (nbase + (size_t)(t - 1) * C_ * HW_);
            lptr[q] = base + gy * W_ + xs;
            sdst[q] = smbase + (uint32_t)(t * PLANEF + r * SROW + ch * 4) * 4u;
        } else {
            lptr[q] = fbase;
            sdst[q] = smbase;
        }
    }
    bool q3 = (tid + 3*256) < LOADS;

    // prefetch channels 0 and 1 (overlaps the threshold math below)
    #pragma unroll
    for (int s = 0; s < 2; s++) {
        uint32_t soff = (uint32_t)s * (CHF * 4u);
        size_t goff = (size_t)s * HW_;
        #pragma unroll
        for (int q = 0; q < 3; q++) CP_ASYNC16(sdst[q] + soff, lptr[q] + goff);
        if (q3) CP_ASYNC16(sdst[3] + soff, lptr[3] + goff);
        CP_COMMIT();
    }

    // census thresholds: inline 3x3 box average of g_S (bit-exact ref order)
    float T1a = 0.f, T1b = 0.f, T2a[N_] = {0,0,0,0}, T2b[N_] = {0,0,0,0};
    if (vA) {
        T1a = box_avg(g_S + (size_t)(b*5 + 0) * HW_, iA, j);
        #pragma unroll
        for (int n = 0; n < N_; n++)
            T2a[n] = box_avg(g_S + (size_t)(b*5 + 1 + n) * HW_, iA, j);
    }
    if (vB) {
        T1b = box_avg(g_S + (size_t)(b*5 + 0) * HW_, iB, j);
        #pragma unroll
        for (int n = 0; n < N_; n++)
            T2b[n] = box_avg(g_S + (size_t)(b*5 + 1 + n) * HW_, iB, j);
    }

    // mA/mB accumulate NEGATIVE mismatch counts via signed dp4a
    int mA[N_] = {0,0,0,0}, mB[N_] = {0,0,0,0};

    #pragma unroll 1
    for (int c = 0; c < CHUNK; c++) {
        CP_WAIT(1);
        __syncthreads();

        if (c + 2 < CHUNK) {
            uint32_t soff = (uint32_t)((c + 2) % 3) * (CHF * 4u);
            size_t goff = (size_t)(c + 2) * HW_;
            #pragma unroll
            for (int q = 0; q < 3; q++) CP_ASYNC16(sdst[q] + soff, lptr[q] + goff);
            if (q3) CP_ASYNC16(sdst[3] + soff, lptr[3] + goff);
        }
        CP_COMMIT();

        if (act) {                     // warp-uniform: tail-tile warps skip compute
            const float* S = &sm[c % 3][0] + (2 * ty) * SROW;

            // feature plane: packed sign bytes for both pixels (7 PRMT each)
            unsigned fA0, fA1, fA2, fB0, fB1, fB2;
            {
                float x[4][3];
                #pragma unroll
                for (int rr = 0; rr < 4; rr++) {
                    x[rr][0] = S[rr * SROW + sx0];
                    x[rr][1] = S[rr * SROW + sx1];
                    x[rr][2] = S[rr * SROW + sx2];
                }
                unsigned uA[9], uB[9];
                #pragma unroll
                for (int dy = 0; dy < 3; dy++)
                    #pragma unroll
                    for (int dx = 0; dx < 3; dx++) {
                        uA[dy*3+dx] = __float_as_uint(x[dy  ][dx] - T1a);
                        uB[dy*3+dx] = __float_as_uint(x[dy+1][dx] - T1b);
                    }
                fA0 = prmt_merge4(uA[0], uA[1], uA[2], uA[3]);
                fA1 = prmt_merge4(uA[4], uA[5], uA[6], uA[7]);
                fA2 = prmt_sign1(uA[8]);
                fB0 = prmt_merge4(uB[0], uB[1], uB[2], uB[3]);
                fB1 = prmt_merge4(uB[4], uB[5], uB[6], uB[7]);
                fB2 = prmt_sign1(uB[8]);
            }
            #pragma unroll
            for (int n = 0; n < N_; n++) {
                const float* Sn = S + (1 + n) * PLANEF;
                float x[4][3];
                #pragma unroll
                for (int rr = 0; rr < 4; rr++) {
                    x[rr][0] = Sn[rr * SROW + sx0];
                    x[rr][1] = Sn[rr * SROW + sx1];
                    x[rr][2] = Sn[rr * SROW + sx2];
                }
                unsigned vAa[9], vBb[9];
                #pragma unroll
                for (int dy = 0; dy < 3; dy++)
                    #pragma unroll
                    for (int dx = 0; dx < 3; dx++) {
                        int k = dy*3 + dx;
                        vAa[k] = __float_as_uint(x[dy  ][dx] - T2a[n]);
                        vBb[k] = __float_as_uint(x[dy+1][dx] - T2b[n]);
                    }
                unsigned a0 = prmt_merge4(vAa[0], vAa[1], vAa[2], vAa[3]);
                unsigned a1 = prmt_merge4(vAa[4], vAa[5], vAa[6], vAa[7]);
                unsigned a2 = prmt_sign1(vAa[8]);
                unsigned b0 = prmt_merge4(vBb[0], vBb[1], vBb[2], vBb[3]);
                unsigned b1 = prmt_merge4(vBb[4], vBb[5], vBb[6], vBb[7]);
                unsigned b2 = prmt_sign1(vBb[8]);
                // XOR of 0x00/0xFF sign bytes = 0xFF per mismatch; dp4a adds -1 each.
                mA[n] = __dp4a((int)(a0 ^ fA0), 0x01010101, mA[n]);
                mA[n] = __dp4a((int)(a1 ^ fA1), 0x01010101, mA[n]);
                mA[n] = __dp4a((int)(a2 ^ fA2), 0x00000001, mA[n]);
                mB[n] = __dp4a((int)(b0 ^ fB0), 0x01010101, mB[n]);
                mB[n] = __dp4a((int)(b1 ^ fB1), 0x01010101, mB[n]);
                mB[n] = __dp4a((int)(b2 ^ fB2), 0x00000001, mB[n]);
            }
        }
    }

    if (vA) {
        #pragma unroll
        for (int n = 0; n < N_; n++)
            atomicAdd(&g_mism[(size_t)(b * N_ + n) * HW_ + pA], -mA[n]);
    }
    if (vB) {
        #pragma unroll
        for (int n = 0; n < N_; n++)
            atomicAdd(&g_mism[(size_t)(b * N_ + n) * HW_ + pB], -mB[n]);
    }
}

// ---------------------------------------------------------------------------
// K4: softmax + weighted fuse; writes bf16 hi/lo TRANSPOSED [b][p][c]
// ---------------------------------------------------------------------------
__global__ __launch_bounds__(256) void fuse_kernel(const float* __restrict__ feat,
                                                   const float* __restrict__ nearby) {
    __shared__ float4 w_s[32];
    __shared__ __nv_bfloat16 s_hi[32][258];
    __shared__ __nv_bfloat16 s_lo[32][258];

    int tid = threadIdx.x;
    int b = blockIdx.y;
    int p0 = blockIdx.x * 32;

    if (tid < 32) {
        int p = p0 + tid;
        int m0 = g_mism[(size_t)(b*N_+0)*HW_ + p];
        int m1 = g_mism[(size_t)(b*N_+1)*HW_ + p];
        int m2 = g_mism[(size_t)(b*N_+2)*HW_ + p];
        int m3 = g_mism[(size_t)(b*N_+3)*HW_ + p];
        int mn = min(min(m0, m1), min(m2, m3));
        float e0 = expf((float)(mn - m0));
        float e1 = expf((float)(mn - m1));
        float e2 = expf((float)(mn - m2));
        float e3 = expf((float)(mn - m3));
        float s = e0 + e1 + e2 + e3;
        w_s[tid] = make_float4(e0 / s, e1 / s, e2 / s, e3 / s);
    }
    __syncthreads();

    int c   = tid >> 3;
    int px0 = (tid & 7) * 4;
    const float* fp = feat   + (size_t)b * C_ * HW_ + p0 + px0;
    const float* np = nearby + (size_t)b * N_ * C_ * HW_ + p0 + px0;
    float4 wv[4] = {w_s[px0], w_s[px0+1], w_s[px0+2], w_s[px0+3]};

    #pragma unroll
    for (int cc = 0; cc < 8; cc++) {
        int cg = cc * 32 + c;
        size_t co = (size_t)cg * HW_;
        float4 fv = *(const float4*)(fp + co);
        float4 a0 = *(const float4*)(np + co);
        float4 a1 = *(const float4*)(np + (size_t)C_ * HW_ + co);
        float4 a2 = *(const float4*)(np + (size_t)2 * C_ * HW_ + co);
        float4 a3 = *(const float4*)(np + (size_t)3 * C_ * HW_ + co);
        float fr[4] = {fv.x, fv.y, fv.z, fv.w};
        float r0[4] = {a0.x, a0.y, a0.z, a0.w};
        float r1[4] = {a1.x, a1.y, a1.z, a1.w};
        float r2[4] = {a2.x, a2.y, a2.z, a2.w};
        float r3[4] = {a3.x, a3.y, a3.z, a3.w};
        #pragma unroll
        for (int e = 0; e < 4; e++) {
            float4 w = wv[e];
            float v = w.x * r0[e];
            v = fmaf(w.y, r1[e], v);
            v = fmaf(w.z, r2[e], v);
            v = fmaf(w.w, r3[e], v);
            v += fr[e];
            __nv_bfloat16 hi = __float2bfloat16(v);
            s_hi[px0 + e][cg] = hi;
            s_lo[px0 + e][cg] = __float2bfloat16(v - __bfloat162float(hi));
        }
    }
    __syncthreads();

    uint32_t* dh = (uint32_t*)g_fhiT + ((size_t)b * PPAD + p0) * (C_/2);
    uint32_t* dl = (uint32_t*)g_floT + ((size_t)b * PPAD + p0) * (C_/2);
    #pragma unroll
    for (int q = 0; q < 16; q++) {
        int w = tid + q * 256;
        int row = w >> 7, cw = w & 127;
        dh[(size_t)row * 128 + cw] = *(const uint32_t*)&s_hi[row][cw * 2];
        dl[(size_t)row * 128 + cw] = *(const uint32_t*)&s_lo[row][cw * 2];
    }
}

// ---------------------------------------------------------------------------
// K5: mma.sync bf16 split GEMM with ldmatrix fragment loads.
// out[b][o][p] = sum_c W[o][c]*F[c][p] + bias[o]
// ---------------------------------------------------------------------------
#define WPITCH 36                       // 32-bit words per smem row
#define ROWB   144                      // bytes per smem row
#define ST_A   18432                    // 128*144 bytes
#define STAGE  36864                    // A + B per stage
#define GEMM_SMEM (2*STAGE)             // 73728

__global__ __launch_bounds__(256, 2)
void gemm_kernel(const float* __restrict__ bias, float* __restrict__ out) {
    extern __shared__ char smem[];
    uint32_t sb = smem_u32(smem);

    int tid = threadIdx.x, wid = tid >> 5, lid = tid & 31;
    int g = lid >> 2, t = lid & 3;
    int wm = wid & 1, wn = wid >> 1;
    int p0 = blockIdx.x * 128, o0 = blockIdx.y * 128, b = blockIdx.z;

    int ldrow = tid >> 3, ldcol = tid & 7;

    int lm = lid >> 3, lr = lid & 7;
    int a_row_l = wm * 64 + (lm & 1) * 8 + lr;
    int a_col_b = ((lm >> 1) * 4) * 4;
    int b_row_l = wn * 32 + lr;
    int b_col_b = ((lm & 1) * 4) * 4;

    float acc[4][4][4];
    #pragma unroll
    for (int i = 0; i < 4; i++)
        #pragma unroll
        for (int j = 0; j < 4; j++)
            #pragma unroll
            for (int k = 0; k < 4; k++) acc[i][j][k] = 0.0f;

    auto load_chunk = [&](int kk) {
        int buf = kk & 1, seg = kk >> 2, cc0 = (kk & 3) * 64;
        const __nv_bfloat16* As = (seg < 2) ? g_whi : g_wlo;
        const __nv_bfloat16* Bs = (seg == 1) ? g_floT : g_fhiT;
        uint32_t da = sb + buf * STAGE;
        uint32_t db = da + ST_A;
        const __nv_bfloat16* ga = As + (size_t)(o0 + ldrow) * C_ + cc0 + ldcol * 8;
        const __nv_bfloat16* gb = Bs + ((size_t)b * PPAD + p0 + ldrow) * C_ + cc0 + ldcol * 8;
        #pragma unroll
        for (int q = 0; q < 4; q++) {
            CP_ASYNC16(da + (ldrow + q*32) * ROWB + ldcol * 16, ga + (size_t)(q*32) * C_);
            CP_ASYNC16(db + (ldrow + q*32) * ROWB + ldcol * 16, gb + (size_t)(q*32) * C_);
        }
        CP_COMMIT();
    };

    load_chunk(0);

    for (int kk = 0; kk < 12; kk++) {
        if (kk + 1 < 12) { load_chunk(kk + 1); CP_WAIT(1); }
        else             { CP_WAIT(0); }
        __syncthreads();

        uint32_t Abase = sb + (kk & 1) * STAGE;
        uint32_t Bbase = Abase + ST_A;

        #pragma unroll
        for (int s = 0; s < 4; s++) {
            uint32_t afr[4][4];
            #pragma unroll
            for (int mf = 0; mf < 4; mf++) {
                uint32_t aaddr = Abase + (uint32_t)((a_row_l + mf*16) * ROWB + s*32 + a_col_b);
                LDSM4(afr[mf][0], afr[mf][1], afr[mf][2], afr[mf][3], aaddr);
            }
            uint32_t bfr[4][2];
            #pragma unroll
            for (int nf = 0; nf < 4; nf++) {
                uint32_t baddr = Bbase + (uint32_t)((b_row_l + nf*8) * ROWB + s*32 + b_col_b);
                LDSM2(bfr[nf][0], bfr[nf][1], baddr);
            }
            #pragma unroll
            for (int mf = 0; mf < 4; mf++)
                #pragma unroll
                for (int nf = 0; nf < 4; nf++)
                    mma16816(acc[mf][nf], afr[mf], bfr[nf]);
        }
        __syncthreads();
    }

    #pragma unroll
    for (int mf = 0; mf < 4; mf++) {
        int o  = o0 + wm * 64 + mf * 16 + g;
        float bv0 = bias[o];
        float bv1 = bias[o + 8];
        float* r0 = out + ((size_t)b * C_ + o    ) * HW_;
        float* r1 = out + ((size_t)b * C_ + o + 8) * HW_;
        #pragma unroll
        for (int nf = 0; nf < 4; nf++) {
            int p = p0 + wn * 32 + nf * 8 + 2 * t;
            if (p < HW_) {
                *(float2*)(r0 + p) = make_float2(acc[mf][nf][0] + bv0, acc[mf][nf][1] + bv0);
                *(float2*)(r1 + p) = make_float2(acc[mf][nf][2] + bv1, acc[mf][nf][3] + bv1);
            }
        }
    }
}

// ---------------------------------------------------------------------------
extern "C" void kernel_launch(void* const* d_in, const int* in_sizes, int n_in,
                              void* d_out, int out_size) {
    const float* feat   = (const float*)d_in[0];
    const float* nearby = (const float*)d_in[1];
    const float* wf     = (const float*)d_in[2];
    const float* bf     = (const float*)d_in[3];
    float* out = (float*)d_out;

    cudaFuncSetAttribute(gemm_kernel, cudaFuncAttributeMaxDynamicSharedMemorySize, GEMM_SMEM);

    // Launch order keeps deps (zero->sim, sum->sim, fuse->gemm, wprep->gemm)
    // while placing fuse at capture slot #4 for next-round profiling.
    zero_mism<<<(B_*N_*HW_ + 255)/256, 256>>>();

    dim3 g1((HW4 + 255) / 256, B_ * (N_ + 1));
    sum_kernel<<<g1, 256>>>(feat, nearby);

    dim3 g3((W_ + TW - 1) / TW, (H_ + TH - 1) / TH, B_ * 8);
    sim_kernel<<<g3, 256>>>(feat, nearby);

    dim3 g4(HW_ / 32, B_);
    fuse_kernel<<<g4, 256>>>(feat, nearby);

    wprep_kernel<<<C_*C_/256, 256>>>(wf);

    dim3 g5(PPAD / 128, C_ / 128, B_);
    gemm_kernel<<<g5, 256, GEMM_SMEM>>>(bf, out);
}